// round 17
// baseline (speedup 1.0000x reference)
#include <cuda_runtime.h>
#include <cuda_fp16.h>
#include <cuda_bf16.h>

// MonotoneActivation: B=4096, G=512, K=4, D=8
// out[b,g,d] = sum_k coef_k * params[g, j_k, d]
//   v0<=v1<=v2<=v3 sorted values of X[b,g,:], coef=[v0,v1-v0,v2-v1,v3-v2]
//   j_0 = 15,  j_k = bitmask{ i : A_i >= v_k }  (tie bits hit zero coef).
//
// R14 lesson: flat at ~24.8us because grid=1024 vs 740 resident CTAs ->
// 2-wave quantization (~28% idle second wave). This round: persistent
// single-wave grid of 8 x 92 = 736 blocks (< 740), each staging its tables
// ONCE and looping over its g-column's b-range with stride 92.

#define B_DIM 4096
#define G_DIM 512
#define TG 64            // g-tables per block
#define THREADS 256
#define TSTRIDE_B 272    // bytes per fp16 table: 16 rows * 16B + 16B pad
#define NBY 92           // blocks per g-column (8*92=736 < 740 resident)
#define NIT (B_DIM / 4)  // 1024 4-row iterations per g-column

typedef unsigned long long u64;

static __device__ __forceinline__ u64 f32x2_pack(float lo, float hi) {
    u64 r; asm("mov.b64 %0, {%1, %2};" : "=l"(r) : "f"(lo), "f"(hi)); return r;
}
static __device__ __forceinline__ u64 f32x2_mul(u64 a, u64 b) {
    u64 d; asm("mul.rn.f32x2 %0, %1, %2;" : "=l"(d) : "l"(a), "l"(b)); return d;
}
static __device__ __forceinline__ u64 f32x2_fma(u64 a, u64 b, u64 c) {
    u64 d; asm("fma.rn.f32x2 %0, %1, %2, %3;" : "=l"(d) : "l"(a), "l"(b), "l"(c)); return d;
}
static __device__ __forceinline__ float2 f32x2_unpack(u64 v) {
    float2 f; asm("mov.b64 {%0, %1}, %2;" : "=f"(f.x), "=f"(f.y) : "l"(v)); return f;
}
static __device__ __forceinline__ u64 h2_to_f32x2(unsigned h) {
    u64 r;
    asm("{\n\t"
        ".reg .b16 l16, h16;\n\t"
        ".reg .f32 lo, hi;\n\t"
        "mov.b32 {l16, h16}, %1;\n\t"
        "cvt.f32.f16 lo, l16;\n\t"
        "cvt.f32.f16 hi, h16;\n\t"
        "mov.b64 %0, {lo, hi};\n\t"
        "}" : "=l"(r) : "r"(h));
    return r;
}
static __device__ __forceinline__ unsigned h2_bits(__half2 h) {
    return *reinterpret_cast<unsigned*>(&h);
}

__global__ __launch_bounds__(THREADS, 5)
void monotone_act_kernel(const float* __restrict__ X,
                         const float* __restrict__ P,
                         float* __restrict__ out)
{
    __shared__ __align__(16) unsigned char sPB[TG * TSTRIDE_B];   // 17408 B

    const int g0 = blockIdx.x * TG;

    // ---- stage TG param tables once, fp32 -> fp16 ----
    const float4* Pv = reinterpret_cast<const float4*>(P + (size_t)g0 * 128);
    #pragma unroll
    for (int i = threadIdx.x; i < TG * 32; i += THREADS) {
        float4 v = __ldg(&Pv[i]);
        __half2 h01 = __floats2half2_rn(v.x, v.y);
        __half2 h23 = __floats2half2_rn(v.z, v.w);
        int gt = i >> 5;
        int w4 = i & 31;
        uint2 u;
        u.x = h2_bits(h01);
        u.y = h2_bits(h23);
        *reinterpret_cast<uint2*>(&sPB[gt * TSTRIDE_B + w4 * 8]) = u;
    }
    __syncthreads();

    const int gl = threadIdx.x & (TG - 1);       // 0..63 (consecutive g in warp)
    const int bl = threadIdx.x >> 6;             // 0..3
    const uint4* tab = reinterpret_cast<const uint4*>(&sPB[gl * TSTRIDE_B]);

    // row 15 used by every pair -> packed f32x2 registers
    u64 f15[4];
    {
        uint4 r = tab[15];
        f15[0] = h2_to_f32x2(r.x);
        f15[1] = h2_to_f32x2(r.y);
        f15[2] = h2_to_f32x2(r.z);
        f15[3] = h2_to_f32x2(r.w);
    }

    const float4* Xv = reinterpret_cast<const float4*>(X);
    float4*       Ov = reinterpret_cast<float4*>(out);

    // persistent loop: iteration itg handles rows b = itg*4 + bl
    int itg = blockIdx.y;
    int t = (((itg << 2) + bl) << 9) + g0 + gl;          // (b<<9) + g
    const int tstep = (NBY * 4) << 9;                    // advance b by NBY*4

    float4 xv_next = __ldcs(&Xv[t]);

    for (; itg < NIT; itg += NBY, t += tstep) {
        float4 xv = xv_next;
        if (itg + NBY < NIT)
            xv_next = __ldcs(&Xv[t + tstep]);

        const float a0 = xv.x, a1 = xv.y, a2 = xv.z, a3 = xv.w;

        // ---- sorted values via min/max network ----
        float m0 = fminf(a0, a1), M0 = fmaxf(a0, a1);
        float m1 = fminf(a2, a3), M1 = fmaxf(a2, a3);
        float v0 = fminf(m0, m1), tm = fmaxf(m0, m1);
        float v3 = fmaxf(M0, M1), sm = fminf(M0, M1);
        float v1 = fminf(tm, sm), v2 = fmaxf(tm, sm);

        const float c0 = v0;
        const float c1 = v1 - v0;
        const float c2 = v2 - v1;
        const float c3 = v3 - v2;

        // ---- direct gather masks: bit i of j_k = (a_i >= v_k) ----
        const int j1 = (int)(a0 >= v1) | ((int)(a1 >= v1) << 1)
                     | ((int)(a2 >= v1) << 2) | ((int)(a3 >= v1) << 3);
        const int j2 = (int)(a0 >= v2) | ((int)(a1 >= v2) << 1)
                     | ((int)(a2 >= v2) << 2) | ((int)(a3 >= v2) << 3);
        const int j3 = (int)(a0 >= v3) | ((int)(a1 >= v3) << 1)
                     | ((int)(a2 >= v3) << 2) | ((int)(a3 >= v3) << 3);

        // ---- fp16 row gathers: one LDS.128 per row ----
        uint4 q1 = tab[j1];
        uint4 q2 = tab[j2];
        uint4 q3 = tab[j3];

        // ---- packed f32x2 accumulation ----
        const u64 c0x = f32x2_pack(c0, c0);
        const u64 c1x = f32x2_pack(c1, c1);
        const u64 c2x = f32x2_pack(c2, c2);
        const u64 c3x = f32x2_pack(c3, c3);

        u64 acc0 = f32x2_mul(c0x, f15[0]);
        u64 acc1 = f32x2_mul(c0x, f15[1]);
        u64 acc2 = f32x2_mul(c0x, f15[2]);
        u64 acc3 = f32x2_mul(c0x, f15[3]);

        acc0 = f32x2_fma(c1x, h2_to_f32x2(q1.x), acc0);
        acc1 = f32x2_fma(c1x, h2_to_f32x2(q1.y), acc1);
        acc2 = f32x2_fma(c1x, h2_to_f32x2(q1.z), acc2);
        acc3 = f32x2_fma(c1x, h2_to_f32x2(q1.w), acc3);

        acc0 = f32x2_fma(c2x, h2_to_f32x2(q2.x), acc0);
        acc1 = f32x2_fma(c2x, h2_to_f32x2(q2.y), acc1);
        acc2 = f32x2_fma(c2x, h2_to_f32x2(q2.z), acc2);
        acc3 = f32x2_fma(c2x, h2_to_f32x2(q2.w), acc3);

        acc0 = f32x2_fma(c3x, h2_to_f32x2(q3.x), acc0);
        acc1 = f32x2_fma(c3x, h2_to_f32x2(q3.y), acc1);
        acc2 = f32x2_fma(c3x, h2_to_f32x2(q3.z), acc2);
        acc3 = f32x2_fma(c3x, h2_to_f32x2(q3.w), acc3);

        float2 o0 = f32x2_unpack(acc0);
        float2 o1 = f32x2_unpack(acc1);
        float2 o2 = f32x2_unpack(acc2);
        float2 o3 = f32x2_unpack(acc3);

        float4 lo, hi;
        lo.x = o0.x; lo.y = o0.y; lo.z = o1.x; lo.w = o1.y;
        hi.x = o2.x; hi.y = o2.y; hi.z = o3.x; hi.w = o3.y;

        __stcs(&Ov[t * 2],     lo);
        __stcs(&Ov[t * 2 + 1], hi);
    }
}

extern "C" void kernel_launch(void* const* d_in, const int* in_sizes, int n_in,
                              void* d_out, int out_size)
{
    const float* X = (const float*)d_in[0];   // (4096, 2048) f32
    const float* P = (const float*)d_in[1];   // (512, 16, 8)  f32
    float* out     = (float*)d_out;           // (4096, 4096) f32

    dim3 grid(G_DIM / TG, NBY);               // (8, 92) = 736 blocks, 1 wave
    monotone_act_kernel<<<grid, THREADS>>>(X, P, out);
}